// round 3
// baseline (speedup 1.0000x reference)
#include <cuda_runtime.h>
#include <cstdint>
#include <math.h>

#define B_DIM 2
#define H_DIM 16
#define S_DIM 2048
#define D_DIM 64
#define E_DIM 1024

// Scratch (allocation-free rule: device globals)
__device__ float g_Q[B_DIM*H_DIM*S_DIM*D_DIM];   // [bh][s][d]
__device__ float g_K[B_DIM*H_DIM*S_DIM*D_DIM];
__device__ float g_V[B_DIM*H_DIM*S_DIM*D_DIM];
__device__ float g_AV[B_DIM*S_DIM*E_DIM];        // [b][s][h*64+d]

// ---------------------------------------------------------------------------
// JAX partitionable-threefry random bits, key (0, 42).
// Element with flat index i gets counters (hi32(i)=0, lo32(i)=i);
// 32-bit draw = x0 ^ x1 after 20 rounds.
// ---------------------------------------------------------------------------
__device__ __forceinline__ uint32_t jax_bits_k42(uint32_t idx) {
  const uint32_t ks0 = 0u;
  const uint32_t ks1 = 42u;
  const uint32_t ks2 = 42u ^ 0x1BD11BDAu;
  uint32_t x0 = ks0;          // c0 (=0) + ks0
  uint32_t x1 = idx + ks1;    // c1 (=idx) + ks1
#define TF_ROUND(r) { x0 += x1; x1 = __funnelshift_l(x1, x1, (r)); x1 ^= x0; }
  TF_ROUND(13) TF_ROUND(15) TF_ROUND(26) TF_ROUND(6)
  x0 += ks1; x1 += ks2 + 1u;
  TF_ROUND(17) TF_ROUND(29) TF_ROUND(16) TF_ROUND(24)
  x0 += ks2; x1 += ks0 + 2u;
  TF_ROUND(13) TF_ROUND(15) TF_ROUND(26) TF_ROUND(6)
  x0 += ks0; x1 += ks1 + 3u;
  TF_ROUND(17) TF_ROUND(29) TF_ROUND(16) TF_ROUND(24)
  x0 += ks1; x1 += ks2 + 4u;
  TF_ROUND(13) TF_ROUND(15) TF_ROUND(26) TF_ROUND(6)
  x0 += ks2; x1 += ks0 + 5u;
#undef TF_ROUND
  return x0 ^ x1;
}

// ---------------------------------------------------------------------------
// SGEMM: C[m,n] = sum_k A[m,k]*B[n,k] + bias[n]
// 128x128 tile, BK=8, 256 threads, 8x8 micro-tile.
// MODE 0: plain row-major store to C (M x N)
// MODE 1: QKV scatter into g_Q/g_K/g_V per-head layout
// ---------------------------------------------------------------------------
template<int MODE>
__global__ void __launch_bounds__(256, 2)
sgemm_kernel(const float* __restrict__ A, const float* __restrict__ Bm,
             const float* __restrict__ bias, float* __restrict__ C,
             int M, int N, int K) {
  __shared__ float As[8][132];
  __shared__ float Bs[8][132];
  const int tid = threadIdx.x;
  const int lm = tid >> 1;           // 0..127
  const int lk = (tid & 1) << 2;     // 0 or 4
  const int m0 = blockIdx.y << 7;
  const int n0 = blockIdx.x << 7;
  const float* Ap = A + (size_t)(m0 + lm) * K + lk;
  const float* Bp = Bm + (size_t)(n0 + lm) * K + lk;
  const int ty = tid >> 4;
  const int tx = tid & 15;

  float acc[8][8];
#pragma unroll
  for (int i = 0; i < 8; i++)
#pragma unroll
    for (int j = 0; j < 8; j++) acc[i][j] = 0.0f;

  float4 av = *(const float4*)Ap;
  float4 bv = *(const float4*)Bp;

  for (int k0 = 0; k0 < K; k0 += 8) {
    As[lk+0][lm] = av.x; As[lk+1][lm] = av.y; As[lk+2][lm] = av.z; As[lk+3][lm] = av.w;
    Bs[lk+0][lm] = bv.x; Bs[lk+1][lm] = bv.y; Bs[lk+2][lm] = bv.z; Bs[lk+3][lm] = bv.w;
    __syncthreads();
    if (k0 + 8 < K) {
      av = *(const float4*)(Ap + k0 + 8);
      bv = *(const float4*)(Bp + k0 + 8);
    }
#pragma unroll
    for (int kk = 0; kk < 8; kk++) {
      float4 a0 = *(const float4*)&As[kk][ty*8];
      float4 a1 = *(const float4*)&As[kk][ty*8+4];
      float4 b0 = *(const float4*)&Bs[kk][tx*8];
      float4 b1 = *(const float4*)&Bs[kk][tx*8+4];
      float a[8] = {a0.x,a0.y,a0.z,a0.w,a1.x,a1.y,a1.z,a1.w};
      float b[8] = {b0.x,b0.y,b0.z,b0.w,b1.x,b1.y,b1.z,b1.w};
#pragma unroll
      for (int i = 0; i < 8; i++)
#pragma unroll
        for (int j = 0; j < 8; j++)
          acc[i][j] = fmaf(a[i], b[j], acc[i][j]);
    }
    __syncthreads();
  }

  const int col0 = n0 + tx*8;
  float4 bias0 = *(const float4*)&bias[col0];
  float4 bias1 = *(const float4*)&bias[col0+4];

  if (MODE == 0) {
#pragma unroll
    for (int i = 0; i < 8; i++) {
      int row = m0 + ty*8 + i;
      float4 o0 = make_float4(acc[i][0]+bias0.x, acc[i][1]+bias0.y,
                              acc[i][2]+bias0.z, acc[i][3]+bias0.w);
      float4 o1 = make_float4(acc[i][4]+bias1.x, acc[i][5]+bias1.y,
                              acc[i][6]+bias1.z, acc[i][7]+bias1.w);
      *(float4*)&C[(size_t)row*N + col0]     = o0;
      *(float4*)&C[(size_t)row*N + col0 + 4] = o1;
    }
  } else {
    // col = t*1024 + h*64 + d ; 8-wide micro column range never crosses a
    // 64-boundary, so (t, h) are constant per thread.
    const int t  = col0 >> 10;
    const int hh = (col0 >> 6) & 15;
    const int d0 = col0 & 63;
    float* dst = (t == 0) ? g_Q : (t == 1) ? g_K : g_V;
#pragma unroll
    for (int i = 0; i < 8; i++) {
      int n  = m0 + ty*8 + i;      // n = b*2048 + s
      int bb = n >> 11;
      int s  = n & 2047;
      size_t idx = (((size_t)bb*H_DIM + hh)*S_DIM + s)*64 + d0;
      float4 o0 = make_float4(acc[i][0]+bias0.x, acc[i][1]+bias0.y,
                              acc[i][2]+bias0.z, acc[i][3]+bias0.w);
      float4 o1 = make_float4(acc[i][4]+bias1.x, acc[i][5]+bias1.y,
                              acc[i][6]+bias1.z, acc[i][7]+bias1.w);
      *(float4*)&dst[idx]     = o0;
      *(float4*)&dst[idx + 4] = o1;
    }
  }
}

// ---------------------------------------------------------------------------
// Fused attention: per block = (q-tile of 128, one (b,h)).
// Loop k-tiles of 64: scores = Q K^T (fp32), p = sigmoid(s/8),
// sample = threefry-uniform < p, out += sample * V.
// smem: Qs[64][132] (d-major), Ks[64][68] (d-major), Vs[64][64], Ps[64][132]
// ---------------------------------------------------------------------------
__global__ void __launch_bounds__(256, 2)
attn_kernel(float* __restrict__ gAV) {
  extern __shared__ float sm[];
  float* Qs = sm;                  // 64 x 132
  float* Ks = sm + 64*132;         // 64 x 68
  float* Vs = Ks + 64*68;          // 64 x 64
  float* Ps = Vs + 64*64;          // 64 x 132

  const int tid = threadIdx.x;
  const int bh  = blockIdx.y;
  const int b   = bh >> 4;
  const int h   = bh & 15;
  const int q0  = blockIdx.x << 7;

  const float* Qg = g_Q + ((size_t)bh * S_DIM + q0) * 64;
  const float* Kg = g_K + (size_t)bh * S_DIM * 64;
  const float* Vg = g_V + (size_t)bh * S_DIM * 64;

  // Load Q tile transposed: Qs[d][q]
  {
    const int r  = tid >> 1;
    const int dh = (tid & 1) * 32;
#pragma unroll
    for (int i = 0; i < 8; i++) {
      float4 v = *(const float4*)&Qg[(size_t)r*64 + dh + i*4];
      Qs[(dh+i*4+0)*132 + r] = v.x;
      Qs[(dh+i*4+1)*132 + r] = v.y;
      Qs[(dh+i*4+2)*132 + r] = v.z;
      Qs[(dh+i*4+3)*132 + r] = v.w;
    }
  }

  const int ty = tid >> 4;    // q group: 8 rows each
  const int tx = tid & 15;    // k/d group: 4 cols each
  float acco[8][4];
#pragma unroll
  for (int i = 0; i < 8; i++)
#pragma unroll
    for (int j = 0; j < 4; j++) acco[i][j] = 0.0f;

  // flat-index row base: (bh*2048 + q) — full batch-inclusive flattened index
  const uint32_t rowbase = ((uint32_t)bh << 11) + (uint32_t)(q0 + ty*8);

  for (int kt = 0; kt < 32; kt++) {
    __syncthreads();   // previous PV done before overwriting K/V/P

    // Load K tile transposed (Ks[d][k]) and V tile natural (Vs[k][d])
    {
      const int r = tid >> 2;
      const float* krow = &Kg[(size_t)(kt*64 + r)*64];
#pragma unroll
      for (int i = 0; i < 4; i++) {
        int d = ((tid & 3) + i*4) * 4;
        float4 v = *(const float4*)&krow[d];
        Ks[(d+0)*68 + r] = v.x;
        Ks[(d+1)*68 + r] = v.y;
        Ks[(d+2)*68 + r] = v.z;
        Ks[(d+3)*68 + r] = v.w;
      }
      const float4* vsrc = (const float4*)&Vg[(size_t)kt*64*64];
      float4* vdst = (float4*)Vs;
#pragma unroll
      for (int i = 0; i < 4; i++) vdst[tid + i*256] = vsrc[tid + i*256];
    }
    __syncthreads();

    // --- QK^T: scores for (q = ty*8+i, k_local = tx*4+j) ---
    float accs[8][4];
#pragma unroll
    for (int i = 0; i < 8; i++)
#pragma unroll
      for (int j = 0; j < 4; j++) accs[i][j] = 0.0f;

#pragma unroll 16
    for (int kk = 0; kk < 64; kk++) {
      float4 a0 = *(const float4*)&Qs[kk*132 + ty*8];
      float4 a1 = *(const float4*)&Qs[kk*132 + ty*8 + 4];
      float4 kv = *(const float4*)&Ks[kk*68 + tx*4];
      float a[8] = {a0.x,a0.y,a0.z,a0.w,a1.x,a1.y,a1.z,a1.w};
      float kf[4] = {kv.x,kv.y,kv.z,kv.w};
#pragma unroll
      for (int i = 0; i < 8; i++)
#pragma unroll
        for (int j = 0; j < 4; j++)
          accs[i][j] = fmaf(a[i], kf[j], accs[i][j]);
    }

    // --- sigmoid + partitionable-threefry bernoulli; write P transposed ---
#pragma unroll
    for (int i = 0; i < 8; i++) {
      uint32_t crow = (rowbase + (uint32_t)i) << 11;   // (bh*2048+q)*2048
#pragma unroll
      for (int j = 0; j < 4; j++) {
        float p = 1.0f / (1.0f + expf(-accs[i][j] * 0.125f));
        uint32_t idx = crow + (uint32_t)(kt*64 + tx*4 + j);
        uint32_t bits = jax_bits_k42(idx);
        float u = __uint_as_float((bits >> 9) | 0x3f800000u) - 1.0f;
        Ps[(tx*4 + j)*132 + (ty*8 + i)] = (u < p) ? 1.0f : 0.0f;
      }
    }
    __syncthreads();

    // --- PV: out[q][d] += P[k][q] * V[k][d] ---
#pragma unroll 16
    for (int kk = 0; kk < 64; kk++) {
      float4 p0 = *(const float4*)&Ps[kk*132 + ty*8];
      float4 p1 = *(const float4*)&Ps[kk*132 + ty*8 + 4];
      float4 vv = *(const float4*)&Vs[kk*64 + tx*4];
      float pf[8] = {p0.x,p0.y,p0.z,p0.w,p1.x,p1.y,p1.z,p1.w};
      float vf[4] = {vv.x,vv.y,vv.z,vv.w};
#pragma unroll
      for (int i = 0; i < 8; i++)
#pragma unroll
        for (int j = 0; j < 4; j++)
          acco[i][j] = fmaf(pf[i], vf[j], acco[i][j]);
    }
  }

  // Store to AV in [b][s][h*64+d] layout for the output projection
#pragma unroll
  for (int i = 0; i < 8; i++) {
    int q = q0 + ty*8 + i;
    size_t idx = ((size_t)(b*S_DIM + q))*E_DIM + h*64 + tx*4;
    *(float4*)&gAV[idx] = make_float4(acco[i][0], acco[i][1], acco[i][2], acco[i][3]);
  }
}

// ---------------------------------------------------------------------------
extern "C" void kernel_launch(void* const* d_in, const int* in_sizes, int n_in,
                              void* d_out, int out_size) {
  // Resolve inputs by element count (robust to any metadata ordering):
  //   x/x1/x2: 4194304 (x = first), qkv_w: 3145728, qkv_b: 3072,
  //   out_w: 1048576, out_b: 1024
  const float *x = nullptr, *qkv_w = nullptr, *qkv_b = nullptr;
  const float *out_w = nullptr, *out_b = nullptr;
  for (int i = 0; i < n_in; i++) {
    int sz = in_sizes[i];
    if (sz == B_DIM*S_DIM*E_DIM) { if (!x) x = (const float*)d_in[i]; }
    else if (sz == 3*E_DIM*E_DIM) qkv_w = (const float*)d_in[i];
    else if (sz == 3*E_DIM)       qkv_b = (const float*)d_in[i];
    else if (sz == E_DIM*E_DIM)   out_w = (const float*)d_in[i];
    else if (sz == E_DIM)         out_b = (const float*)d_in[i];
  }
  float* out = (float*)d_out;

  float* gav_ptr = nullptr;
  cudaGetSymbolAddress((void**)&gav_ptr, g_AV);

  // 1) QKV = x @ qkv_w^T + qkv_b, scattered per-head
  sgemm_kernel<1><<<dim3(3*E_DIM/128, (B_DIM*S_DIM)/128), 256>>>(
      x, qkv_w, qkv_b, nullptr, B_DIM*S_DIM, 3*E_DIM, E_DIM);

  // 2) fused attention (scores -> sigmoid -> threefry bernoulli -> PV)
  size_t smem = (size_t)(64*132 + 64*68 + 64*64 + 64*132) * sizeof(float);
  cudaFuncSetAttribute(attn_kernel, cudaFuncAttributeMaxDynamicSharedMemorySize,
                       (int)smem);
  attn_kernel<<<dim3(S_DIM/128, B_DIM*H_DIM), 256, smem>>>(gav_ptr);

  // 3) out = AV @ out_w^T + out_b
  sgemm_kernel<0><<<dim3(E_DIM/128, (B_DIM*S_DIM)/128), 256>>>(
      gav_ptr, out_w, out_b, out, B_DIM*S_DIM, E_DIM, E_DIM);
}

// round 7
// speedup vs baseline: 1.2404x; 1.2404x over previous
#include <cuda_runtime.h>
#include <cstdint>
#include <math.h>

#define B_DIM 2
#define H_DIM 16
#define S_DIM 2048
#define E_DIM 1024

// Scratch (allocation-free rule: device globals)
__device__ float g_Q[B_DIM*H_DIM*S_DIM*64];   // [bh][s][d]
__device__ float g_K[B_DIM*H_DIM*S_DIM*64];
__device__ float g_V[B_DIM*H_DIM*S_DIM*64];
__device__ float g_AV[B_DIM*S_DIM*E_DIM];     // [b][s][h*64+d]

// ===========================================================================
// bf16 mma.sync helpers (base PTX, sm_80+)
// ===========================================================================
__device__ __forceinline__ uint32_t pack_bf16(float lo, float hi) {
  uint32_t r;  // PTX: first src -> upper half, second src -> lower half
  asm("cvt.rn.satfinite.bf16x2.f32 %0, %1, %2;" : "=r"(r) : "f"(hi), "f"(lo));
  return r;
}
__device__ __forceinline__ float lo_f(uint32_t u) {
  return __uint_as_float(u << 16);
}
__device__ __forceinline__ float hi_f(uint32_t u) {
  return __uint_as_float(u & 0xFFFF0000u);
}
__device__ __forceinline__ void split3(float fe, float fo,
                                       uint32_t& h, uint32_t& m, uint32_t& l) {
  h = pack_bf16(fe, fo);
  float re = fe - lo_f(h);
  float ro = fo - hi_f(h);
  m = pack_bf16(re, ro);
  l = pack_bf16(re - lo_f(m), ro - hi_f(m));
}
__device__ __forceinline__ void mma_bf16(float* c, const uint32_t* a,
                                         uint32_t b0, uint32_t b1) {
  asm volatile(
      "mma.sync.aligned.m16n8k16.row.col.f32.bf16.bf16.f32 "
      "{%0,%1,%2,%3},{%4,%5,%6,%7},{%8,%9},{%0,%1,%2,%3};"
      : "+f"(c[0]), "+f"(c[1]), "+f"(c[2]), "+f"(c[3])
      : "r"(a[0]), "r"(a[1]), "r"(a[2]), "r"(a[3]), "r"(b0), "r"(b1));
}

// ===========================================================================
// JAX partitionable-threefry random bits, key (0, 42).
// ===========================================================================
__device__ __forceinline__ uint32_t jax_bits_k42(uint32_t idx) {
  const uint32_t ks0 = 0u;
  const uint32_t ks1 = 42u;
  const uint32_t ks2 = 42u ^ 0x1BD11BDAu;
  uint32_t x0 = ks0;
  uint32_t x1 = idx + ks1;
#define TF_ROUND(r) { x0 += x1; x1 = __funnelshift_l(x1, x1, (r)); x1 ^= x0; }
  TF_ROUND(13) TF_ROUND(15) TF_ROUND(26) TF_ROUND(6)
  x0 += ks1; x1 += ks2 + 1u;
  TF_ROUND(17) TF_ROUND(29) TF_ROUND(16) TF_ROUND(24)
  x0 += ks2; x1 += ks0 + 2u;
  TF_ROUND(13) TF_ROUND(15) TF_ROUND(26) TF_ROUND(6)
  x0 += ks0; x1 += ks1 + 3u;
  TF_ROUND(17) TF_ROUND(29) TF_ROUND(16) TF_ROUND(24)
  x0 += ks1; x1 += ks2 + 4u;
  TF_ROUND(13) TF_ROUND(15) TF_ROUND(26) TF_ROUND(6)
  x0 += ks2; x1 += ks0 + 5u;
#undef TF_ROUND
  return x0 ^ x1;
}

// ===========================================================================
// Proven r3 fp32 SIMT SGEMM (MODE 1: QKV scatter). 128x128, BK=8.
// ===========================================================================
__global__ void __launch_bounds__(256, 2)
sgemm_qkv(const float* __restrict__ A, const float* __restrict__ Bm,
          const float* __restrict__ bias) {
  __shared__ float As[8][132];
  __shared__ float Bs[8][132];
  const int tid = threadIdx.x;
  const int lm = tid >> 1;
  const int lk = (tid & 1) << 2;
  const int m0 = blockIdx.y << 7;
  const int n0 = blockIdx.x << 7;
  const float* Ap = A + (size_t)(m0 + lm) * 1024 + lk;
  const float* Bp = Bm + (size_t)(n0 + lm) * 1024 + lk;
  const int ty = tid >> 4;
  const int tx = tid & 15;

  float acc[8][8];
#pragma unroll
  for (int i = 0; i < 8; i++)
#pragma unroll
    for (int j = 0; j < 8; j++) acc[i][j] = 0.0f;

  float4 av = *(const float4*)Ap;
  float4 bv = *(const float4*)Bp;

  for (int k0 = 0; k0 < 1024; k0 += 8) {
    As[lk+0][lm] = av.x; As[lk+1][lm] = av.y; As[lk+2][lm] = av.z; As[lk+3][lm] = av.w;
    Bs[lk+0][lm] = bv.x; Bs[lk+1][lm] = bv.y; Bs[lk+2][lm] = bv.z; Bs[lk+3][lm] = bv.w;
    __syncthreads();
    if (k0 + 8 < 1024) {
      av = *(const float4*)(Ap + k0 + 8);
      bv = *(const float4*)(Bp + k0 + 8);
    }
#pragma unroll
    for (int kk = 0; kk < 8; kk++) {
      float4 a0 = *(const float4*)&As[kk][ty*8];
      float4 a1 = *(const float4*)&As[kk][ty*8+4];
      float4 b0 = *(const float4*)&Bs[kk][tx*8];
      float4 b1 = *(const float4*)&Bs[kk][tx*8+4];
      float a[8] = {a0.x,a0.y,a0.z,a0.w,a1.x,a1.y,a1.z,a1.w};
      float b[8] = {b0.x,b0.y,b0.z,b0.w,b1.x,b1.y,b1.z,b1.w};
#pragma unroll
      for (int i = 0; i < 8; i++)
#pragma unroll
        for (int j = 0; j < 8; j++)
          acc[i][j] = fmaf(a[i], b[j], acc[i][j]);
    }
    __syncthreads();
  }

  const int col0 = n0 + tx*8;
  float4 bias0 = *(const float4*)&bias[col0];
  float4 bias1 = *(const float4*)&bias[col0+4];
  const int t  = col0 >> 10;
  const int hh = (col0 >> 6) & 15;
  const int d0 = col0 & 63;
  float* dst = (t == 0) ? g_Q : (t == 1) ? g_K : g_V;
#pragma unroll
  for (int i = 0; i < 8; i++) {
    int n  = m0 + ty*8 + i;
    int bb = n >> 11;
    int s  = n & 2047;
    size_t idx = (((size_t)bb*H_DIM + hh)*S_DIM + s)*64 + d0;
    float4 o0 = make_float4(acc[i][0]+bias0.x, acc[i][1]+bias0.y,
                            acc[i][2]+bias0.z, acc[i][3]+bias0.w);
    float4 o1 = make_float4(acc[i][4]+bias1.x, acc[i][5]+bias1.y,
                            acc[i][6]+bias1.z, acc[i][7]+bias1.w);
    *(float4*)&dst[idx]     = o0;
    *(float4*)&dst[idx + 4] = o1;
  }
}

// ===========================================================================
// bf16x3 tensor GEMM for the output projection (MODE 0 only).
// CTA 128x128, 8 warps (4m x 2n), m16n8k16.
// ===========================================================================
__global__ void __launch_bounds__(256, 2)
bf16_proj(const float* __restrict__ A, const float* __restrict__ W,
          const float* __restrict__ bias, float* __restrict__ C) {
  __shared__ float As[16][132];
  __shared__ float Ws[16][132];
  const int tid  = threadIdx.x;
  const int lane = tid & 31;
  const int warp = tid >> 5;
  const int g    = lane >> 2;
  const int tg   = lane & 3;
  const int wm   = warp & 3;
  const int wn   = warp >> 2;
  const int m0   = blockIdx.y << 7;
  const int n0   = blockIdx.x << 7;

  const int lm = tid & 127;
  const int lk = (tid >> 7) << 3;
  const float* Ap = A + (size_t)(m0 + lm) * 1024 + lk;
  const float* Wp = W + (size_t)(n0 + lm) * 1024 + lk;

  float c[2][8][4];
#pragma unroll
  for (int mt = 0; mt < 2; mt++)
#pragma unroll
    for (int nt = 0; nt < 8; nt++)
#pragma unroll
      for (int r = 0; r < 4; r++) c[mt][nt][r] = 0.0f;

  float4 av0 = *(const float4*)Ap;
  float4 av1 = *(const float4*)(Ap + 4);
  float4 wv0 = *(const float4*)Wp;
  float4 wv1 = *(const float4*)(Wp + 4);

  for (int k0 = 0; k0 < 1024; k0 += 16) {
    As[lk+0][lm] = av0.x; As[lk+1][lm] = av0.y;
    As[lk+2][lm] = av0.z; As[lk+3][lm] = av0.w;
    As[lk+4][lm] = av1.x; As[lk+5][lm] = av1.y;
    As[lk+6][lm] = av1.z; As[lk+7][lm] = av1.w;
    Ws[lk+0][lm] = wv0.x; Ws[lk+1][lm] = wv0.y;
    Ws[lk+2][lm] = wv0.z; Ws[lk+3][lm] = wv0.w;
    Ws[lk+4][lm] = wv1.x; Ws[lk+5][lm] = wv1.y;
    Ws[lk+6][lm] = wv1.z; Ws[lk+7][lm] = wv1.w;
    __syncthreads();
    if (k0 + 16 < 1024) {
      av0 = *(const float4*)(Ap + k0 + 16);
      av1 = *(const float4*)(Ap + k0 + 20);
      wv0 = *(const float4*)(Wp + k0 + 16);
      wv1 = *(const float4*)(Wp + k0 + 20);
    }

    uint32_t Ah[2][4], Am[2][4], Al[2][4];
#pragma unroll
    for (int mt = 0; mt < 2; mt++) {
      const int r0 = wm*32 + mt*16 + g;
      const int ke = 2*tg;
#pragma unroll
      for (int p = 0; p < 4; p++) {
        const int kk = ke + ((p & 2) ? 8 : 0);
        const int rr = r0 + ((p & 1) ? 8 : 0);
        split3(As[kk][rr], As[kk+1][rr], Ah[mt][p], Am[mt][p], Al[mt][p]);
      }
    }

#pragma unroll
    for (int nt = 0; nt < 8; nt++) {
      const int n = wn*64 + nt*8 + g;
      const int ke = 2*tg;
      uint32_t Bh0, Bm0, Bl0, Bh1, Bm1, Bl1;
      split3(Ws[ke][n],   Ws[ke+1][n], Bh0, Bm0, Bl0);
      split3(Ws[ke+8][n], Ws[ke+9][n], Bh1, Bm1, Bl1);
#pragma unroll
      for (int mt = 0; mt < 2; mt++) {
        mma_bf16(c[mt][nt], Ah[mt], Bh0, Bh1);   // hh
        mma_bf16(c[mt][nt], Ah[mt], Bm0, Bm1);   // hm
        mma_bf16(c[mt][nt], Am[mt], Bh0, Bh1);   // mh
      }
    }
    __syncthreads();
  }

#pragma unroll
  for (int nt = 0; nt < 8; nt++) {
    const int col = n0 + wn*64 + nt*8 + tg*2;
    const float bx = bias[col], by = bias[col+1];
#pragma unroll
    for (int mt = 0; mt < 2; mt++) {
      const int row = m0 + wm*32 + mt*16 + g;
      *(float2*)&C[(size_t)row     * E_DIM + col] =
          make_float2(c[mt][nt][0] + bx, c[mt][nt][1] + by);
      *(float2*)&C[(size_t)(row+8) * E_DIM + col] =
          make_float2(c[mt][nt][2] + bx, c[mt][nt][3] + by);
    }
  }
}

// ===========================================================================
// Fused attention: SIMT fp32 QK^T + sigmoid + threefry (BIT-IDENTICAL to r3)
// + tensor bf16x2 PV (P exact in bf16, V = vh+vl split).
// smem: Qs f32[64][132], Ks f32[64][68], Pp u32[128][36],
//       Vh u32[64][36], Vl u32[64][36]   (88064 bytes)
// ===========================================================================
#define PP_OFF  (64*132 + 64*68)            // float index of Pp
#define VH_OFF  (PP_OFF + 128*36)
#define VL_OFF  (VH_OFF + 64*36)
#define ATTN_SMEM ((VL_OFF + 64*36) * 4)

__global__ void __launch_bounds__(256, 2)
attn_kernel(float* __restrict__ gAV) {
  extern __shared__ float smf[];
  float* Qs = smf;                       // 64 x 132 (d-major)
  float* Ks = smf + 64*132;              // 64 x 68  (d-major)
  uint32_t* Pp = (uint32_t*)(smf + PP_OFF);   // [q][36] packed k-pairs
  uint32_t* Vh = (uint32_t*)(smf + VH_OFF);   // [d][36] packed k-pairs (hi)
  uint32_t* Vl = (uint32_t*)(smf + VL_OFF);   // [d][36] packed k-pairs (lo)

  const int tid = threadIdx.x;
  const int lane = tid & 31;
  const int warp = tid >> 5;
  const int bh  = blockIdx.y;
  const int b   = bh >> 4;
  const int h   = bh & 15;
  const int q0  = blockIdx.x << 7;

  const float* Qg = g_Q + ((size_t)bh * S_DIM + q0) * 64;
  const float* Kg = g_K + (size_t)bh * S_DIM * 64;
  const float* Vg = g_V + (size_t)bh * S_DIM * 64;

  // Load Q tile transposed: Qs[d][q]
  {
    const int r  = tid >> 1;
    const int dh = (tid & 1) * 32;
#pragma unroll
    for (int i = 0; i < 8; i++) {
      float4 v = *(const float4*)&Qg[(size_t)r*64 + dh + i*4];
      Qs[(dh+i*4+0)*132 + r] = v.x;
      Qs[(dh+i*4+1)*132 + r] = v.y;
      Qs[(dh+i*4+2)*132 + r] = v.z;
      Qs[(dh+i*4+3)*132 + r] = v.w;
    }
  }

  const int ty = tid >> 4;    // q group for SIMT QK
  const int tx = tid & 15;    // k group for SIMT QK

  // PV mma fragment coords
  const int g2  = lane >> 2;
  const int tg2 = lane & 3;
  const int wm2 = warp & 3;   // q 32-row group
  const int wn2 = warp >> 2;  // d 32-col group

  float co[2][4][4];          // PV accumulators (c fragments)
#pragma unroll
  for (int mt = 0; mt < 2; mt++)
#pragma unroll
    for (int nt = 0; nt < 4; nt++)
#pragma unroll
      for (int r = 0; r < 4; r++) co[mt][nt][r] = 0.0f;

  const uint32_t rowbase = ((uint32_t)bh << 11) + (uint32_t)(q0 + ty*8);

  for (int kt = 0; kt < 32; kt++) {
    __syncthreads();   // previous PV / QK done before overwriting K/V/Pp

    // Load K tile transposed (Ks[d][k])
    {
      const int r = tid >> 2;
      const float* krow = &Kg[(size_t)(kt*64 + r)*64];
#pragma unroll
      for (int i = 0; i < 4; i++) {
        int d = ((tid & 3) + i*4) * 4;
        float4 v = *(const float4*)&krow[d];
        Ks[(d+0)*68 + r] = v.x;
        Ks[(d+1)*68 + r] = v.y;
        Ks[(d+2)*68 + r] = v.z;
        Ks[(d+3)*68 + r] = v.w;
      }
    }
    // Load V tile, split bf16 h/l, pack k-pairs: Vh/Vl[d][kpair]
    {
#pragma unroll
      for (int r = 0; r < 2; r++) {
        const int w  = tid + r*256;      // 512 items
        const int kp = w & 31;           // k-pair 0..31
        const int d0 = (w >> 5) * 4;     // d group
        const float* v0 = &Vg[(size_t)(kt*64 + 2*kp)*64 + d0];
        float4 a = *(const float4*)v0;
        float4 bvv = *(const float4*)(v0 + 64);
        float va[4] = {a.x, a.y, a.z, a.w};
        float vb[4] = {bvv.x, bvv.y, bvv.z, bvv.w};
#pragma unroll
        for (int e = 0; e < 4; e++) {
          uint32_t hp = pack_bf16(va[e], vb[e]);
          uint32_t lp = pack_bf16(va[e] - lo_f(hp), vb[e] - hi_f(hp));
          Vh[(d0+e)*36 + kp] = hp;
          Vl[(d0+e)*36 + kp] = lp;
        }
      }
    }
    __syncthreads();

    // --- SIMT QK^T (bit-identical to r3) ---
    float accs[8][4];
#pragma unroll
    for (int i = 0; i < 8; i++)
#pragma unroll
      for (int j = 0; j < 4; j++) accs[i][j] = 0.0f;

#pragma unroll 16
    for (int kk = 0; kk < 64; kk++) {
      float4 a0 = *(const float4*)&Qs[kk*132 + ty*8];
      float4 a1 = *(const float4*)&Qs[kk*132 + ty*8 + 4];
      float4 kv = *(const float4*)&Ks[kk*68 + tx*4];
      float a[8] = {a0.x,a0.y,a0.z,a0.w,a1.x,a1.y,a1.z,a1.w};
      float kf[4] = {kv.x,kv.y,kv.z,kv.w};
#pragma unroll
      for (int i = 0; i < 8; i++)
#pragma unroll
        for (int j = 0; j < 4; j++)
          accs[i][j] = fmaf(a[i], kf[j], accs[i][j]);
    }

    // --- sigmoid + threefry bernoulli; pack P pairs into Pp[q][kpair] ---
#pragma unroll
    for (int i = 0; i < 8; i++) {
      uint32_t crow = (rowbase + (uint32_t)i) << 11;
      float s[4];
#pragma unroll
      for (int j = 0; j < 4; j++) {
        float p = 1.0f / (1.0f + expf(-accs[i][j] * 0.125f));
        uint32_t idx = crow + (uint32_t)(kt*64 + tx*4 + j);
        uint32_t bits = jax_bits_k42(idx);
        float u = __uint_as_float((bits >> 9) | 0x3f800000u) - 1.0f;
        s[j] = (u < p) ? 1.0f : 0.0f;
      }
      const int q = ty*8 + i;
      Pp[q*36 + tx*2    ] = pack_bf16(s[0], s[1]);
      Pp[q*36 + tx*2 + 1] = pack_bf16(s[2], s[3]);
    }
    __syncthreads();

    // --- PV via bf16 mma: out[q][d] += P[q][k] * (Vh+Vl)[k][d] ---
#pragma unroll
    for (int c4 = 0; c4 < 4; c4++) {         // k16 chunks
      uint32_t a[2][4];
#pragma unroll
      for (int mt = 0; mt < 2; mt++) {
        const int row = wm2*32 + mt*16 + g2;
        a[mt][0] = Pp[row    *36 + c4*8 + tg2];
        a[mt][1] = Pp[(row+8)*36 + c4*8 + tg2];
        a[mt][2] = Pp[row    *36 + c4*8 + tg2 + 4];
        a[mt][3] = Pp[(row+8)*36 + c4*8 + tg2 + 4];
      }
#pragma unroll
      for (int nt = 0; nt < 4; nt++) {
        const int d = wn2*32 + nt*8 + g2;
        uint32_t bh0 = Vh[d*36 + c4*8 + tg2];
        uint32_t bh1 = Vh[d*36 + c4*8 + tg2 + 4];
        uint32_t bl0 = Vl[d*36 + c4*8 + tg2];
        uint32_t bl1 = Vl[d*36 + c4*8 + tg2 + 4];
#pragma unroll
        for (int mt = 0; mt < 2; mt++) {
          mma_bf16(co[mt][nt], a[mt], bh0, bh1);
          mma_bf16(co[mt][nt], a[mt], bl0, bl1);
        }
      }
    }
  }

  // Store PV c-fragments to g_AV [b][s][h*64+d]
#pragma unroll
  for (int mt = 0; mt < 2; mt++) {
    const int q = q0 + wm2*32 + mt*16 + g2;
#pragma unroll
    for (int nt = 0; nt < 4; nt++) {
      const int d = wn2*32 + nt*8 + tg2*2;
      size_t base = ((size_t)(b*S_DIM + q))*E_DIM + h*64 + d;
      *(float2*)&gAV[base] = make_float2(co[mt][nt][0], co[mt][nt][1]);
      *(float2*)&gAV[base + (size_t)8*E_DIM] =
          make_float2(co[mt][nt][2], co[mt][nt][3]);
    }
  }
}

// ===========================================================================
extern "C" void kernel_launch(void* const* d_in, const int* in_sizes, int n_in,
                              void* d_out, int out_size) {
  const float *x = nullptr, *qkv_w = nullptr, *qkv_b = nullptr;
  const float *out_w = nullptr, *out_b = nullptr;
  for (int i = 0; i < n_in; i++) {
    int sz = in_sizes[i];
    if (sz == B_DIM*S_DIM*E_DIM) { if (!x) x = (const float*)d_in[i]; }
    else if (sz == 3*E_DIM*E_DIM) qkv_w = (const float*)d_in[i];
    else if (sz == 3*E_DIM)       qkv_b = (const float*)d_in[i];
    else if (sz == E_DIM*E_DIM)   out_w = (const float*)d_in[i];
    else if (sz == E_DIM)         out_b = (const float*)d_in[i];
  }
  float* out = (float*)d_out;

  float* gav_ptr = nullptr;
  cudaGetSymbolAddress((void**)&gav_ptr, g_AV);

  // 1) QKV = x @ qkv_w^T + qkv_b — proven fp32 SIMT, per-head scatter
  sgemm_qkv<<<dim3(3*E_DIM/128, (B_DIM*S_DIM)/128), 256>>>(x, qkv_w, qkv_b);

  // 2) fused attention: SIMT QK + threefry (r3-identical) + tensor bf16x2 PV
  cudaFuncSetAttribute(attn_kernel, cudaFuncAttributeMaxDynamicSharedMemorySize,
                       ATTN_SMEM);
  attn_kernel<<<dim3(S_DIM/128, B_DIM*H_DIM), 256, ATTN_SMEM>>>(gav_ptr);

  // 3) out = AV @ out_w^T + out_b — tensor bf16x3 (direct error only)
  bf16_proj<<<dim3(E_DIM/128, (B_DIM*S_DIM)/128), 256>>>(
      gav_ptr, out_w, out_b, out);
}

// round 8
// speedup vs baseline: 1.3315x; 1.0735x over previous
#include <cuda_runtime.h>
#include <cstdint>
#include <math.h>

#define B_DIM 2
#define H_DIM 16
#define S_DIM 2048
#define E_DIM 1024

// Scratch (allocation-free rule: device globals)
__device__ float g_Q[B_DIM*H_DIM*S_DIM*64];   // [bh][s][d]
__device__ float g_K[B_DIM*H_DIM*S_DIM*64];
__device__ float g_V[B_DIM*H_DIM*S_DIM*64];
__device__ float g_AV[B_DIM*S_DIM*E_DIM];     // [b][s][h*64+d]

// ===========================================================================
// bf16 mma.sync helpers (base PTX, sm_80+)
// ===========================================================================
__device__ __forceinline__ uint32_t pack_bf16(float lo, float hi) {
  uint32_t r;  // PTX: first src -> upper half, second src -> lower half
  asm("cvt.rn.satfinite.bf16x2.f32 %0, %1, %2;" : "=r"(r) : "f"(hi), "f"(lo));
  return r;
}
__device__ __forceinline__ float lo_f(uint32_t u) {
  return __uint_as_float(u << 16);
}
__device__ __forceinline__ float hi_f(uint32_t u) {
  return __uint_as_float(u & 0xFFFF0000u);
}
__device__ __forceinline__ void split3(float fe, float fo,
                                       uint32_t& h, uint32_t& m, uint32_t& l) {
  h = pack_bf16(fe, fo);
  float re = fe - lo_f(h);
  float ro = fo - hi_f(h);
  m = pack_bf16(re, ro);
  l = pack_bf16(re - lo_f(m), ro - hi_f(m));
}
__device__ __forceinline__ void mma_bf16(float* c, const uint32_t* a,
                                         uint32_t b0, uint32_t b1) {
  asm volatile(
      "mma.sync.aligned.m16n8k16.row.col.f32.bf16.bf16.f32 "
      "{%0,%1,%2,%3},{%4,%5,%6,%7},{%8,%9},{%0,%1,%2,%3};"
      : "+f"(c[0]), "+f"(c[1]), "+f"(c[2]), "+f"(c[3])
      : "r"(a[0]), "r"(a[1]), "r"(a[2]), "r"(a[3]), "r"(b0), "r"(b1));
}

// ===========================================================================
// JAX partitionable-threefry random bits, key (0, 42).
// ===========================================================================
__device__ __forceinline__ uint32_t jax_bits_k42(uint32_t idx) {
  const uint32_t ks0 = 0u;
  const uint32_t ks1 = 42u;
  const uint32_t ks2 = 42u ^ 0x1BD11BDAu;
  uint32_t x0 = ks0;
  uint32_t x1 = idx + ks1;
#define TF_ROUND(r) { x0 += x1; x1 = __funnelshift_l(x1, x1, (r)); x1 ^= x0; }
  TF_ROUND(13) TF_ROUND(15) TF_ROUND(26) TF_ROUND(6)
  x0 += ks1; x1 += ks2 + 1u;
  TF_ROUND(17) TF_ROUND(29) TF_ROUND(16) TF_ROUND(24)
  x0 += ks2; x1 += ks0 + 2u;
  TF_ROUND(13) TF_ROUND(15) TF_ROUND(26) TF_ROUND(6)
  x0 += ks0; x1 += ks1 + 3u;
  TF_ROUND(17) TF_ROUND(29) TF_ROUND(16) TF_ROUND(24)
  x0 += ks1; x1 += ks2 + 4u;
  TF_ROUND(13) TF_ROUND(15) TF_ROUND(26) TF_ROUND(6)
  x0 += ks2; x1 += ks0 + 5u;
#undef TF_ROUND
  return x0 ^ x1;
}

// ===========================================================================
// Proven r3 fp32 SIMT SGEMM (QKV scatter). 128x128, BK=8.
// ===========================================================================
__global__ void __launch_bounds__(256, 2)
sgemm_qkv(const float* __restrict__ A, const float* __restrict__ Bm,
          const float* __restrict__ bias) {
  __shared__ float As[8][132];
  __shared__ float Bs[8][132];
  const int tid = threadIdx.x;
  const int lm = tid >> 1;
  const int lk = (tid & 1) << 2;
  const int m0 = blockIdx.y << 7;
  const int n0 = blockIdx.x << 7;
  const float* Ap = A + (size_t)(m0 + lm) * 1024 + lk;
  const float* Bp = Bm + (size_t)(n0 + lm) * 1024 + lk;
  const int ty = tid >> 4;
  const int tx = tid & 15;

  float acc[8][8];
#pragma unroll
  for (int i = 0; i < 8; i++)
#pragma unroll
    for (int j = 0; j < 8; j++) acc[i][j] = 0.0f;

  float4 av = *(const float4*)Ap;
  float4 bv = *(const float4*)Bp;

  for (int k0 = 0; k0 < 1024; k0 += 8) {
    As[lk+0][lm] = av.x; As[lk+1][lm] = av.y; As[lk+2][lm] = av.z; As[lk+3][lm] = av.w;
    Bs[lk+0][lm] = bv.x; Bs[lk+1][lm] = bv.y; Bs[lk+2][lm] = bv.z; Bs[lk+3][lm] = bv.w;
    __syncthreads();
    if (k0 + 8 < 1024) {
      av = *(const float4*)(Ap + k0 + 8);
      bv = *(const float4*)(Bp + k0 + 8);
    }
#pragma unroll
    for (int kk = 0; kk < 8; kk++) {
      float4 a0 = *(const float4*)&As[kk][ty*8];
      float4 a1 = *(const float4*)&As[kk][ty*8+4];
      float4 b0 = *(const float4*)&Bs[kk][tx*8];
      float4 b1 = *(const float4*)&Bs[kk][tx*8+4];
      float a[8] = {a0.x,a0.y,a0.z,a0.w,a1.x,a1.y,a1.z,a1.w};
      float b[8] = {b0.x,b0.y,b0.z,b0.w,b1.x,b1.y,b1.z,b1.w};
#pragma unroll
      for (int i = 0; i < 8; i++)
#pragma unroll
        for (int j = 0; j < 8; j++)
          acc[i][j] = fmaf(a[i], b[j], acc[i][j]);
    }
    __syncthreads();
  }

  const int col0 = n0 + tx*8;
  float4 bias0 = *(const float4*)&bias[col0];
  float4 bias1 = *(const float4*)&bias[col0+4];
  const int t  = col0 >> 10;
  const int hh = (col0 >> 6) & 15;
  const int d0 = col0 & 63;
  float* dst = (t == 0) ? g_Q : (t == 1) ? g_K : g_V;
#pragma unroll
  for (int i = 0; i < 8; i++) {
    int n  = m0 + ty*8 + i;
    int bb = n >> 11;
    int s  = n & 2047;
    size_t idx = (((size_t)bb*H_DIM + hh)*S_DIM + s)*64 + d0;
    float4 o0 = make_float4(acc[i][0]+bias0.x, acc[i][1]+bias0.y,
                            acc[i][2]+bias0.z, acc[i][3]+bias0.w);
    float4 o1 = make_float4(acc[i][4]+bias1.x, acc[i][5]+bias1.y,
                            acc[i][6]+bias1.z, acc[i][7]+bias1.w);
    *(float4*)&dst[idx]     = o0;
    *(float4*)&dst[idx + 4] = o1;
  }
}

// ===========================================================================
// bf16x3 tensor GEMM for the output projection (proven r7).
// ===========================================================================
__global__ void __launch_bounds__(256, 2)
bf16_proj(const float* __restrict__ A, const float* __restrict__ W,
          const float* __restrict__ bias, float* __restrict__ C) {
  __shared__ float As[16][132];
  __shared__ float Ws[16][132];
  const int tid  = threadIdx.x;
  const int lane = tid & 31;
  const int warp = tid >> 5;
  const int g    = lane >> 2;
  const int tg   = lane & 3;
  const int wm   = warp & 3;
  const int wn   = warp >> 2;
  const int m0   = blockIdx.y << 7;
  const int n0   = blockIdx.x << 7;

  const int lm = tid & 127;
  const int lk = (tid >> 7) << 3;
  const float* Ap = A + (size_t)(m0 + lm) * 1024 + lk;
  const float* Wp = W + (size_t)(n0 + lm) * 1024 + lk;

  float c[2][8][4];
#pragma unroll
  for (int mt = 0; mt < 2; mt++)
#pragma unroll
    for (int nt = 0; nt < 8; nt++)
#pragma unroll
      for (int r = 0; r < 4; r++) c[mt][nt][r] = 0.0f;

  float4 av0 = *(const float4*)Ap;
  float4 av1 = *(const float4*)(Ap + 4);
  float4 wv0 = *(const float4*)Wp;
  float4 wv1 = *(const float4*)(Wp + 4);

  for (int k0 = 0; k0 < 1024; k0 += 16) {
    As[lk+0][lm] = av0.x; As[lk+1][lm] = av0.y;
    As[lk+2][lm] = av0.z; As[lk+3][lm] = av0.w;
    As[lk+4][lm] = av1.x; As[lk+5][lm] = av1.y;
    As[lk+6][lm] = av1.z; As[lk+7][lm] = av1.w;
    Ws[lk+0][lm] = wv0.x; Ws[lk+1][lm] = wv0.y;
    Ws[lk+2][lm] = wv0.z; Ws[lk+3][lm] = wv0.w;
    Ws[lk+4][lm] = wv1.x; Ws[lk+5][lm] = wv1.y;
    Ws[lk+6][lm] = wv1.z; Ws[lk+7][lm] = wv1.w;
    __syncthreads();
    if (k0 + 16 < 1024) {
      av0 = *(const float4*)(Ap + k0 + 16);
      av1 = *(const float4*)(Ap + k0 + 20);
      wv0 = *(const float4*)(Wp + k0 + 16);
      wv1 = *(const float4*)(Wp + k0 + 20);
    }

    uint32_t Ah[2][4], Am[2][4], Al[2][4];
#pragma unroll
    for (int mt = 0; mt < 2; mt++) {
      const int r0 = wm*32 + mt*16 + g;
      const int ke = 2*tg;
#pragma unroll
      for (int p = 0; p < 4; p++) {
        const int kk = ke + ((p & 2) ? 8 : 0);
        const int rr = r0 + ((p & 1) ? 8 : 0);
        split3(As[kk][rr], As[kk+1][rr], Ah[mt][p], Am[mt][p], Al[mt][p]);
      }
    }

#pragma unroll
    for (int nt = 0; nt < 8; nt++) {
      const int n = wn*64 + nt*8 + g;
      const int ke = 2*tg;
      uint32_t Bh0, Bm0, Bl0, Bh1, Bm1, Bl1;
      split3(Ws[ke][n],   Ws[ke+1][n], Bh0, Bm0, Bl0);
      split3(Ws[ke+8][n], Ws[ke+9][n], Bh1, Bm1, Bl1);
#pragma unroll
      for (int mt = 0; mt < 2; mt++) {
        mma_bf16(c[mt][nt], Ah[mt], Bh0, Bh1);   // hh
        mma_bf16(c[mt][nt], Ah[mt], Bm0, Bm1);   // hm
        mma_bf16(c[mt][nt], Am[mt], Bh0, Bh1);   // mh
      }
    }
    __syncthreads();
  }

#pragma unroll
  for (int nt = 0; nt < 8; nt++) {
    const int col = n0 + wn*64 + nt*8 + tg*2;
    const float bx = bias[col], by = bias[col+1];
#pragma unroll
    for (int mt = 0; mt < 2; mt++) {
      const int row = m0 + wm*32 + mt*16 + g;
      *(float2*)&C[(size_t)row     * E_DIM + col] =
          make_float2(c[mt][nt][0] + bx, c[mt][nt][1] + by);
      *(float2*)&C[(size_t)(row+8) * E_DIM + col] =
          make_float2(c[mt][nt][2] + bx, c[mt][nt][3] + by);
    }
  }
}

// ===========================================================================
// Fused attention, full tensor-core version:
//   QK^T: bf16x6 mma (4 k16 chunks over D=64 — short chain, RZ-bias safe)
//   sigmoid + threefry: SIMT (byte-identical math to r3/r7)
//   PV:   bf16x2 mma (proven r7)
// smem (u32 units): Qs f32 128x72 | Kh/Km/Kl 64x36 | Pp 128x36 | Vh/Vl 64x36
// ===========================================================================
#define QS_STRIDE 72
#define KH_OFF  9216
#define KM_OFF  (KH_OFF + 2304)
#define KL_OFF  (KM_OFF + 2304)
#define PP_OFF  (KL_OFF + 2304)
#define VH_OFF  (PP_OFF + 4608)
#define VL_OFF  (VH_OFF + 2304)
#define ATTN_SMEM ((VL_OFF + 2304) * 4)   // 101376 bytes

__global__ void __launch_bounds__(256, 2)
attn_kernel(float* __restrict__ gAV) {
  extern __shared__ float smf[];
  float*    Qs = smf;                          // [q][72] fp32
  uint32_t* Kh = (uint32_t*)(smf + KH_OFF);    // [k][36]
  uint32_t* Km = (uint32_t*)(smf + KM_OFF);
  uint32_t* Kl = (uint32_t*)(smf + KL_OFF);
  uint32_t* Pp = (uint32_t*)(smf + PP_OFF);    // [q][36] packed k-pairs
  uint32_t* Vh = (uint32_t*)(smf + VH_OFF);    // [d][36] packed k-pairs
  uint32_t* Vl = (uint32_t*)(smf + VL_OFF);

  const int tid  = threadIdx.x;
  const int lane = tid & 31;
  const int warp = tid >> 5;
  const int g    = lane >> 2;
  const int tg   = lane & 3;
  const int bh   = blockIdx.y;
  const int b    = bh >> 4;
  const int h    = bh & 15;
  const int q0   = blockIdx.x << 7;

  // QK warp map: 4 q-groups x 2 k-groups (warp tile 32q x 32k)
  const int wq = warp & 3;
  const int wk = warp >> 2;
  // PV warp map: 4 q-groups x 2 d-groups (proven r7)
  const int wm2 = warp & 3;
  const int wn2 = warp >> 2;

  const float* Qg = g_Q + ((size_t)bh * S_DIM + q0) * 64;
  const float* Kg = g_K + (size_t)bh * S_DIM * 64;
  const float* Vg = g_V + (size_t)bh * S_DIM * 64;

  // Load Q tile fp32: Qs[q][d], stride 72
  {
#pragma unroll
    for (int i = 0; i < 8; i++) {
      const int idx = tid + i*256;       // 2048 float4s
      const int row = idx >> 4;
      const int c4  = idx & 15;
      float4 v = *(const float4*)&Qg[(size_t)row*64 + c4*4];
      *(float4*)&Qs[row*QS_STRIDE + c4*4] = v;
    }
  }

  float co[2][4][4];   // PV accumulators
#pragma unroll
  for (int mt = 0; mt < 2; mt++)
#pragma unroll
    for (int nt = 0; nt < 4; nt++)
#pragma unroll
      for (int r = 0; r < 4; r++) co[mt][nt][r] = 0.0f;

  const uint32_t cbase = ((uint32_t)bh << 11) + (uint32_t)q0;

  for (int kt = 0; kt < 32; kt++) {
    __syncthreads();   // previous PV done before overwriting K/V/Pp

    // --- stage K split: Kh/Km/Kl[k][dpair] ---
    {
      const int r = tid >> 2;            // 0..63
      const float* krow = &Kg[(size_t)(kt*64 + r)*64];
      const int base = r*36;
#pragma unroll
      for (int i = 0; i < 4; i++) {
        const int d4 = (tid & 3)*4 + i;  // float4 index 0..15
        float4 v = *(const float4*)&krow[d4*4];
        uint32_t h0, m0_, l0, h1, m1, l1;
        split3(v.x, v.y, h0, m0_, l0);
        split3(v.z, v.w, h1, m1, l1);
        Kh[base + d4*2]     = h0;  Km[base + d4*2]     = m0_;  Kl[base + d4*2]     = l0;
        Kh[base + d4*2 + 1] = h1;  Km[base + d4*2 + 1] = m1;  Kl[base + d4*2 + 1] = l1;
      }
    }
    // --- stage V split: Vh/Vl[d][kpair] (proven r7) ---
    {
#pragma unroll
      for (int r = 0; r < 2; r++) {
        const int w  = tid + r*256;
        const int kp = w & 31;
        const int d0 = (w >> 5) * 4;
        const float* v0 = &Vg[(size_t)(kt*64 + 2*kp)*64 + d0];
        float4 a = *(const float4*)v0;
        float4 bvv = *(const float4*)(v0 + 64);
        float va[4] = {a.x, a.y, a.z, a.w};
        float vb[4] = {bvv.x, bvv.y, bvv.z, bvv.w};
#pragma unroll
        for (int e = 0; e < 4; e++) {
          uint32_t hp = pack_bf16(va[e], vb[e]);
          uint32_t lp = pack_bf16(va[e] - lo_f(hp), vb[e] - hi_f(hp));
          Vh[(d0+e)*36 + kp] = hp;
          Vl[(d0+e)*36 + kp] = lp;
        }
      }
    }
    __syncthreads();

    // --- QK^T via bf16x6 mma: c[q 2x16][k 4x8] ---
    float c[2][4][4];
#pragma unroll
    for (int mt = 0; mt < 2; mt++)
#pragma unroll
      for (int nt = 0; nt < 4; nt++)
#pragma unroll
        for (int r = 0; r < 4; r++) c[mt][nt][r] = 0.0f;

#pragma unroll
    for (int c4 = 0; c4 < 4; c4++) {
      const int k0 = c4*16 + 2*tg;
      uint32_t Ah[2][4], Am[2][4], Al[2][4];
#pragma unroll
      for (int mt = 0; mt < 2; mt++) {
        const float* q0p = &Qs[(wq*32 + mt*16 + g)*QS_STRIDE];
        const float* q8p = q0p + 8*QS_STRIDE;
        float2 v00 = *(const float2*)&q0p[k0];
        float2 v01 = *(const float2*)&q8p[k0];
        float2 v10 = *(const float2*)&q0p[k0+8];
        float2 v11 = *(const float2*)&q8p[k0+8];
        split3(v00.x, v00.y, Ah[mt][0], Am[mt][0], Al[mt][0]);
        split3(v01.x, v01.y, Ah[mt][1], Am[mt][1], Al[mt][1]);
        split3(v10.x, v10.y, Ah[mt][2], Am[mt][2], Al[mt][2]);
        split3(v11.x, v11.y, Ah[mt][3], Am[mt][3], Al[mt][3]);
      }
#pragma unroll
      for (int nt = 0; nt < 4; nt++) {
        const int col = wk*32 + nt*8 + g;
        const int kb  = col*36 + c4*8;
        uint32_t Bh0 = Kh[kb+tg], Bh1 = Kh[kb+tg+4];
        uint32_t Bm0 = Km[kb+tg], Bm1 = Km[kb+tg+4];
        uint32_t Bl0 = Kl[kb+tg], Bl1 = Kl[kb+tg+4];
#pragma unroll
        for (int mt = 0; mt < 2; mt++) {
          mma_bf16(c[mt][nt], Ah[mt], Bh0, Bh1);  // hh
          mma_bf16(c[mt][nt], Ah[mt], Bm0, Bm1);  // hm
          mma_bf16(c[mt][nt], Am[mt], Bh0, Bh1);  // mh
          mma_bf16(c[mt][nt], Ah[mt], Bl0, Bl1);  // hl
          mma_bf16(c[mt][nt], Am[mt], Bm0, Bm1);  // mm
          mma_bf16(c[mt][nt], Al[mt], Bh0, Bh1);  // lh
        }
      }
    }

    // --- sigmoid + threefry bernoulli; pack P pairs into Pp ---
    const uint32_t ktk = (uint32_t)(kt*64);
#pragma unroll
    for (int mt = 0; mt < 2; mt++) {
      const int qA = wq*32 + mt*16 + g;
      const uint32_t row0 = (cbase + (uint32_t)qA) << 11;
      const uint32_t row8 = (cbase + (uint32_t)(qA+8)) << 11;
#pragma unroll
      for (int nt = 0; nt < 4; nt++) {
        const uint32_t kl = ktk + (uint32_t)(wk*32 + nt*8 + 2*tg);
        float p0 = 1.0f / (1.0f + expf(-c[mt][nt][0] * 0.125f));
        float p1 = 1.0f / (1.0f + expf(-c[mt][nt][1] * 0.125f));
        float p2 = 1.0f / (1.0f + expf(-c[mt][nt][2] * 0.125f));
        float p3 = 1.0f / (1.0f + expf(-c[mt][nt][3] * 0.125f));
        uint32_t b0 = jax_bits_k42(row0 + kl);
        uint32_t b1 = jax_bits_k42(row0 + kl + 1u);
        uint32_t b2 = jax_bits_k42(row8 + kl);
        uint32_t b3 = jax_bits_k42(row8 + kl + 1u);
        float u0 = __uint_as_float((b0 >> 9) | 0x3f800000u) - 1.0f;
        float u1 = __uint_as_float((b1 >> 9) | 0x3f800000u) - 1.0f;
        float u2 = __uint_as_float((b2 >> 9) | 0x3f800000u) - 1.0f;
        float u3 = __uint_as_float((b3 >> 9) | 0x3f800000u) - 1.0f;
        const int kp = wk*16 + nt*4 + tg;
        Pp[qA*36 + kp]     = pack_bf16(u0 < p0 ? 1.0f : 0.0f,
                                       u1 < p1 ? 1.0f : 0.0f);
        Pp[(qA+8)*36 + kp] = pack_bf16(u2 < p2 ? 1.0f : 0.0f,
                                       u3 < p3 ? 1.0f : 0.0f);
      }
    }
    __syncthreads();

    // --- PV via bf16x2 mma (proven r7) ---
#pragma unroll
    for (int c4 = 0; c4 < 4; c4++) {
      uint32_t a[2][4];
#pragma unroll
      for (int mt = 0; mt < 2; mt++) {
        const int row = wm2*32 + mt*16 + g;
        a[mt][0] = Pp[row    *36 + c4*8 + tg];
        a[mt][1] = Pp[(row+8)*36 + c4*8 + tg];
        a[mt][2] = Pp[row    *36 + c4*8 + tg + 4];
        a[mt][3] = Pp[(row+8)*36 + c4*8 + tg + 4];
      }
#pragma unroll
      for (int nt = 0; nt < 4; nt++) {
        const int d = wn2*32 + nt*8 + g;
        uint32_t bh0 = Vh[d*36 + c4*8 + tg];
        uint32_t bh1 = Vh[d*36 + c4*8 + tg + 4];
        uint32_t bl0 = Vl[d*36 + c4*8 + tg];
        uint32_t bl1 = Vl[d*36 + c4*8 + tg + 4];
#pragma unroll
        for (int mt = 0; mt < 2; mt++) {
          mma_bf16(co[mt][nt], a[mt], bh0, bh1);
          mma_bf16(co[mt][nt], a[mt], bl0, bl1);
        }
      }
    }
  }

  // Store PV c-fragments to g_AV [b][s][h*64+d] (proven r7)
#pragma unroll
  for (int mt = 0; mt < 2; mt++) {
    const int q = q0 + wm2*32 + mt*16 + g;
#pragma unroll
    for (int nt = 0; nt < 4; nt++) {
      const int d = wn2*32 + nt*8 + tg*2;
      size_t base = ((size_t)(b*S_DIM + q))*E_DIM + h*64 + d;
      *(float2*)&gAV[base] = make_float2(co[mt][nt][0], co[mt][nt][1]);
      *(float2*)&gAV[base + (size_t)8*E_DIM] =
          make_float2(co[mt][nt][2], co[mt][nt][3]);
    }
  }
}

// ===========================================================================
extern "C" void kernel_launch(void* const* d_in, const int* in_sizes, int n_in,
                              void* d_out, int out_size) {
  const float *x = nullptr, *qkv_w = nullptr, *qkv_b = nullptr;
  const float *out_w = nullptr, *out_b = nullptr;
  for (int i = 0; i < n_in; i++) {
    int sz = in_sizes[i];
    if (sz == B_DIM*S_DIM*E_DIM) { if (!x) x = (const float*)d_in[i]; }
    else if (sz == 3*E_DIM*E_DIM) qkv_w = (const float*)d_in[i];
    else if (sz == 3*E_DIM)       qkv_b = (const float*)d_in[i];
    else if (sz == E_DIM*E_DIM)   out_w = (const float*)d_in[i];
    else if (sz == E_DIM)         out_b = (const float*)d_in[i];
  }
  float* out = (float*)d_out;

  float* gav_ptr = nullptr;
  cudaGetSymbolAddress((void**)&gav_ptr, g_AV);

  // 1) QKV = x @ qkv_w^T + qkv_b — proven fp32 SIMT, per-head scatter
  sgemm_qkv<<<dim3(3*E_DIM/128, (B_DIM*S_DIM)/128), 256>>>(x, qkv_w, qkv_b);

  // 2) fused attention: tensor bf16x6 QK + threefry + tensor bf16x2 PV
  cudaFuncSetAttribute(attn_kernel, cudaFuncAttributeMaxDynamicSharedMemorySize,
                       ATTN_SMEM);
  attn_kernel<<<dim3(S_DIM/128, B_DIM*H_DIM), 256, ATTN_SMEM>>>(gav_ptr);

  // 3) out = AV @ out_w^T + out_b — tensor bf16x3
  bf16_proj<<<dim3(E_DIM/128, (B_DIM*S_DIM)/128), 256>>>(
      gav_ptr, out_w, out_b, out);
}